// round 15
// baseline (speedup 1.0000x reference)
#include <cuda_runtime.h>
#include <cuda_fp16.h>
#include <math.h>
#include <stdint.h>

#define B_  2
#define S_  2048
#define E_  1024
#define H_  16
#define HD_ 64
#define M_  (B_*S_)   // 4096

// Scratch (allocation-free rule: __device__ globals), all fp16
__device__ __half g_Xh[M_*E_];        // rounded X
__device__ __half g_Wh[4][E_*E_];     // rounded Wq,Wk,Wv,Wo
__device__ __half g_Qh[B_*S_*E_];     // * 0.125*log2(e)
__device__ __half g_Kh[B_*S_*E_];
__device__ __half g_Vth[B_*H_*HD_*S_];// [b][h][d][s]
__device__ __half g_ctxh[B_*S_*E_];   // [B][H][S][HD] order

// ============================================================
// helpers
// ============================================================
__device__ __forceinline__ void mma16(float c[4], const uint32_t a[4],
                                      uint32_t b0, uint32_t b1) {
    asm volatile(
        "mma.sync.aligned.m16n8k16.row.col.f32.f16.f16.f32 "
        "{%0,%1,%2,%3}, {%4,%5,%6,%7}, {%8,%9}, {%0,%1,%2,%3};"
        : "+f"(c[0]), "+f"(c[1]), "+f"(c[2]), "+f"(c[3])
        : "r"(a[0]), "r"(a[1]), "r"(a[2]), "r"(a[3]), "r"(b0), "r"(b1));
}

__device__ __forceinline__ void ldmx4(uint32_t r[4], uint32_t addr) {
    asm volatile("ldmatrix.sync.aligned.m8n8.x4.shared.b16 {%0,%1,%2,%3}, [%4];"
                 : "=r"(r[0]), "=r"(r[1]), "=r"(r[2]), "=r"(r[3]) : "r"(addr));
}

__device__ __forceinline__ uint32_t smem_u32(const void* p) {
    uint32_t a;
    asm("{ .reg .u64 t; cvta.to.shared.u64 t, %1; cvt.u32.u64 %0, t; }"
        : "=r"(a) : "l"(p));
    return a;
}

__device__ __forceinline__ void cpasync16(uint32_t dst, const void* src) {
    asm volatile(
        "{ .reg .u64 g; cvta.to.global.u64 g, %1; "
        "cp.async.cg.shared.global [%0], [g], 16; }"
        :: "r"(dst), "l"(src) : "memory");
}
#define CP_COMMIT() asm volatile("cp.async.commit_group;" ::: "memory")
#define CP_WAIT0()  asm volatile("cp.async.wait_group 0;" ::: "memory")
#define CP_WAIT3()  asm volatile("cp.async.wait_group 3;" ::: "memory")

// fp16 ldmatrix lane->byte-offset maps (stride ST in halves)
// A-operand [m][k]: tiles (m0,k0),(m8,k0),(m0,k8),(m8,k8)
#define ALANE16(lane, ST) (((((lane)&7) + (((lane)>>3)&1)*8) * (ST) + ((lane)>>4)*8) * 2)
// B-operand [n][k]: tiles (n0,k0),(n0,k8),(n8,k0),(n8,k8)
#define BLANE16(lane, ST) (((((lane)&7) + ((lane)>>4)*8) * (ST) + (((lane)>>3)&1)*8) * 2)

// ============================================================
// prepass: round X and the 4 weights to fp16
// ============================================================
__global__ __launch_bounds__(256) void prep_kernel(
    const float* __restrict__ X,
    const float* __restrict__ Wq, const float* __restrict__ Wk,
    const float* __restrict__ Wv, const float* __restrict__ Wo)
{
    const int seg = blockIdx.y;
    const float* src; __half* dst; int n;
    if (seg == 0)      { src = X;  dst = g_Xh;    n = M_ * E_; }
    else if (seg == 1) { src = Wq; dst = g_Wh[0]; n = E_ * E_; }
    else if (seg == 2) { src = Wk; dst = g_Wh[1]; n = E_ * E_; }
    else if (seg == 3) { src = Wv; dst = g_Wh[2]; n = E_ * E_; }
    else               { src = Wo; dst = g_Wh[3]; n = E_ * E_; }
    const int i = (blockIdx.x * 256 + threadIdx.x) * 4;
    if (i < n) {
        float4 v = *(const float4*)(src + i);
        *(half2*)(dst + i)     = __floats2half2_rn(v.x, v.y);
        *(half2*)(dst + i + 2) = __floats2half2_rn(v.z, v.w);
    }
}

// ============================================================
// GEMM core (fp16): 128x128 tile, BK=32 halves, 5-stage cp.async (wait 3),
// 256 threads (8 warps 2x4), 4x4 m16n8k16 per warp, ldmatrix frags
// (unchanged from R14 — proven structure)
// ============================================================
#define GSTH   40                   // halves per row (32 + 8 pad); 80B rows
#define GBUFB  (128 * GSTH * 2)     // 10240 bytes per stage per matrix
#define GSTAGES 5
#define GEMM_SMEM (GSTAGES * 2 * GBUFB)   // 102400 bytes
#define GNKT   32                   // K = 1024 / 32

__device__ __forceinline__ void gemm_core(const __half* __restrict__ A,
                                          const __half* __restrict__ W,
                                          char* smem,
                                          float acc[4][4][4],
                                          int bm, int bn)
{
    char* As = smem;
    char* Bs = smem + GSTAGES * GBUFB;

    const int tid  = threadIdx.x;
    const int lane = tid & 31;
    const int wid  = tid >> 5;
    const int warp_m = wid >> 2;
    const int warp_n = wid & 3;

    // loader: 2 threads per row, each 2 x 16B chunks (16 halves)
    const int lrow = tid >> 1;           // 0..127
    const int lc0  = (tid & 1) * 16;     // half offset 0 or 16

    const uint32_t sA = smem_u32(As);
    const uint32_t sB = smem_u32(Bs);
    const uint32_t aL = sA + (uint32_t)(warp_m * 64 * GSTH * 2) + ALANE16(lane, GSTH);
    const uint32_t bL = sB + (uint32_t)(warp_n * 32 * GSTH * 2) + BLANE16(lane, GSTH);
    const uint32_t dA = sA + (uint32_t)((lrow * GSTH + lc0) * 2);
    const uint32_t dB = sB + (uint32_t)((lrow * GSTH + lc0) * 2);

    const __half* Ap = A + (size_t)(bm + lrow) * E_ + lc0;
    const __half* Wp = W + (size_t)(bn + lrow) * E_ + lc0;

#pragma unroll
    for (int mi = 0; mi < 4; mi++)
#pragma unroll
        for (int nt = 0; nt < 4; nt++)
#pragma unroll
            for (int j = 0; j < 4; j++) acc[mi][nt][j] = 0.f;

    // prologue: issue stages 0..3
#pragma unroll
    for (int s = 0; s < GSTAGES - 1; ++s) {
        const int k0 = s * 32;
        cpasync16(dA + s * GBUFB,      Ap + k0);
        cpasync16(dA + s * GBUFB + 16, Ap + k0 + 8);
        cpasync16(dB + s * GBUFB,      Wp + k0);
        cpasync16(dB + s * GBUFB + 16, Wp + k0 + 8);
        CP_COMMIT();
    }

    int cslot = 0, wslot = GSTAGES - 1;
    for (int kt = 0; kt < GNKT; ++kt) {
        CP_WAIT3();            // tile kt resident (<=3 groups pending)
        __syncthreads();       // all warps past compute(kt-1); data published

        {   // issue tile kt+4 into wslot (empty commit at tail keeps counts)
            const int t = kt + GSTAGES - 1;
            if (t < GNKT) {
                const int k0 = t * 32;
                cpasync16(dA + wslot * GBUFB,      Ap + k0);
                cpasync16(dA + wslot * GBUFB + 16, Ap + k0 + 8);
                cpasync16(dB + wslot * GBUFB,      Wp + k0);
                cpasync16(dB + wslot * GBUFB + 16, Wp + k0 + 8);
            }
            CP_COMMIT();
        }

        const uint32_t aB = aL + cslot * GBUFB;
        const uint32_t bB = bL + cslot * GBUFB;
#pragma unroll
        for (int ks = 0; ks < 2; ks++) {
            uint32_t af[4][4];
#pragma unroll
            for (int mi = 0; mi < 4; mi++)
                ldmx4(af[mi], aB + mi * (16 * GSTH * 2) + ks * 32);
            uint32_t bf[2][4];
#pragma unroll
            for (int np = 0; np < 2; np++)
                ldmx4(bf[np], bB + np * (16 * GSTH * 2) + ks * 32);
#pragma unroll
            for (int np = 0; np < 2; np++)
#pragma unroll
                for (int hh = 0; hh < 2; hh++) {
                    const int nt = np * 2 + hh;
#pragma unroll
                    for (int mi = 0; mi < 4; mi++)
                        mma16(acc[mi][nt], af[mi], bf[np][hh * 2], bf[np][hh * 2 + 1]);
                }
        }

        cslot = (cslot == GSTAGES - 1) ? 0 : cslot + 1;
        wslot = (wslot == GSTAGES - 1) ? 0 : wslot + 1;
    }
}

// ============================================================
// qkv: X @ W^T + b -> Qh (*0.125*log2e) / Kh / Vth (transposed)
// ============================================================
#define QSCALE (0.125f * 1.4426950408889634f)

__global__ __launch_bounds__(256, 2) void qkv_kernel(
    const float* __restrict__ bq, const float* __restrict__ bk,
    const float* __restrict__ bv)
{
    extern __shared__ char smem[];
    const int z = blockIdx.z;
    const float* bias = (z == 0) ? bq : (z == 1) ? bk : bv;
    const int bm = blockIdx.y * 128;
    const int bn = blockIdx.x * 128;

    float acc[4][4][4];
    gemm_core(g_Xh, g_Wh[z], smem, acc, bm, bn);

    const int lane = threadIdx.x & 31;
    const int wid  = threadIdx.x >> 5;
    const int g    = lane >> 2;
    const int tig  = lane & 3;
    const int warp_m = wid >> 2;
    const int warp_n = wid & 3;

    if (z < 2) {
        __half* C = (z == 0) ? g_Qh : g_Kh;
        const float scale = (z == 0) ? QSCALE : 1.0f;
#pragma unroll
        for (int mi = 0; mi < 4; mi++) {
            const int r0 = bm + warp_m * 64 + mi * 16 + g;
#pragma unroll
            for (int nt = 0; nt < 4; nt++) {
                const int col = bn + warp_n * 32 + nt * 8 + 2 * tig;
                float bx = bias[col], by = bias[col + 1];
                *(half2*)(C + (size_t)r0 * E_ + col) =
                    __floats2half2_rn((acc[mi][nt][0] + bx) * scale,
                                      (acc[mi][nt][1] + by) * scale);
                *(half2*)(C + (size_t)(r0 + 8) * E_ + col) =
                    __floats2half2_rn((acc[mi][nt][2] + bx) * scale,
                                      (acc[mi][nt][3] + by) * scale);
            }
        }
    } else {
        // V: transposed store into g_Vth[b][h][d][s]
#pragma unroll
        for (int mi = 0; mi < 4; mi++) {
            const int r0 = bm + warp_m * 64 + mi * 16 + g;
#pragma unroll
            for (int nt = 0; nt < 4; nt++) {
                const int col = bn + warp_n * 32 + nt * 8 + 2 * tig;
                float bx = bias[col], by = bias[col + 1];
#pragma unroll
                for (int rr = 0; rr < 2; rr++) {
                    const int row = r0 + rr * 8;
                    const int s  = row & (S_ - 1);
                    const int bb = row >> 11;
                    const int h0 = col >> 6, d0 = col & 63;
                    const int h1 = (col + 1) >> 6, d1 = (col + 1) & 63;
                    g_Vth[(((size_t)bb * H_ + h0) * HD_ + d0) * S_ + s] =
                        __float2half_rn(acc[mi][nt][rr * 2 + 0] + bx);
                    g_Vth[(((size_t)bb * H_ + h1) * HD_ + d1) * S_ + s] =
                        __float2half_rn(acc[mi][nt][rr * 2 + 1] + by);
                }
            }
        }
    }
}

// ============================================================
// oproj: ctx @ Wo^T + bo -> out (fp32)
// ============================================================
__global__ __launch_bounds__(256, 2) void oproj_kernel(
    const float* __restrict__ bo, float* __restrict__ out)
{
    extern __shared__ char smem[];
    const int bm = blockIdx.y * 128;
    const int bn = blockIdx.x * 128;

    float acc[4][4][4];
    gemm_core(g_ctxh, g_Wh[3], smem, acc, bm, bn);

    const int lane = threadIdx.x & 31;
    const int wid  = threadIdx.x >> 5;
    const int g    = lane >> 2;
    const int tig  = lane & 3;
    const int warp_m = wid >> 2;
    const int warp_n = wid & 3;

#pragma unroll
    for (int mi = 0; mi < 4; mi++) {
        const int r0 = bm + warp_m * 64 + mi * 16 + g;
#pragma unroll
        for (int nt = 0; nt < 4; nt++) {
            const int col = bn + warp_n * 32 + nt * 8 + 2 * tig;
            float bx = bo[col], by = bo[col + 1];
            *(float2*)(out + (size_t)r0 * E_ + col) =
                make_float2(acc[mi][nt][0] + bx, acc[mi][nt][1] + by);
            *(float2*)(out + (size_t)(r0 + 8) * E_ + col) =
                make_float2(acc[mi][nt][2] + bx, acc[mi][nt][3] + by);
        }
    }
}

// ============================================================
// Flash attention (fp16 mma): 64-query x 64-key tiles, 128 threads
// (4 warps), 4 CTAs/SM. Per-warp work identical to R14 (16 q-rows x
// 64 keys); smaller barrier domain + cross-CTA overlap hide stalls.
// ============================================================
#define TQ    64
#define APH   72
#define KVBB  (64 * APH * 2)        // 9216 bytes per K/V buffer
#define ATTN_SMEM (4 * KVBB + TQ * APH * 2)   // 46080 bytes

__global__ __launch_bounds__(128, 4) void attn_kernel()
{
    extern __shared__ char sm[];
    char*   Kb  = sm;                       // [2][64][APH] halves (rows = key)
    char*   Vb  = sm + 2 * KVBB;            // [2][64][APH]  (rows = d, cols = key)
    __half* QPh = (__half*)(sm + 4 * KVBB); // [64][APH]   Q tile then Ps

    const int b  = blockIdx.z;
    const int h  = blockIdx.y;
    const int q0 = blockIdx.x * TQ;
    const int tid  = threadIdx.x;
    const int lane = tid & 31;
    const int wid  = tid >> 5;              // 0..3
    const int g    = lane >> 2;
    const int tig  = lane & 3;
    const int r0   = wid * 16 + g;          // 0..63

    const uint32_t sKb = smem_u32(Kb);
    const uint32_t sVb = smem_u32(Vb);
    const uint32_t sQP = smem_u32(QPh);
    const uint32_t qpL = sQP + (uint32_t)(wid * 16 * APH * 2) + ALANE16(lane, APH);

    const __half* Qg  = g_Qh + (size_t)b * S_ * E_ + (size_t)h * HD_;
    const __half* Kg  = g_Kh + (size_t)b * S_ * E_ + (size_t)h * HD_;
    const __half* Vtg = g_Vth + (size_t)(b * H_ + h) * HD_ * S_;

    // K/V loader: 2 threads per row, each 4 x 16B (32 halves)
    const int lrow = tid >> 1;            // 0..63 (key for K, d for V)
    const int lc0  = (tid & 1) * 32;      // half offset 0 or 32
    const uint32_t dK = sKb + (uint32_t)((lrow * APH + lc0) * 2);
    const uint32_t dV = sVb + (uint32_t)((lrow * APH + lc0) * 2);

    // ---- Q tile fill (64 rows x 64 halves) ----
    {
        const int row = tid >> 1;
        const int c0  = (tid & 1) * 32;
        const __half* Qr = Qg + (size_t)(q0 + row) * E_ + c0;
#pragma unroll
        for (int p = 0; p < 4; ++p)
            *(uint4*)&QPh[row * APH + c0 + p * 8] = *(const uint4*)(Qr + p * 8);
    }

    // ---- issue K/V tile 0 ----
    {
        const __half* Ks = Kg + (size_t)lrow * E_;
        const __half* Vs = Vtg + (size_t)lrow * S_;
#pragma unroll
        for (int p = 0; p < 4; ++p) {
            cpasync16(dK + p * 16, Ks + lc0 + p * 8);
            cpasync16(dV + p * 16, Vs + lc0 + p * 8);
        }
        CP_COMMIT();
    }

    __syncthreads();   // Q tile visible

    // hoist Q fragments: 4 k16-steps
    uint32_t qf[4][4];
#pragma unroll
    for (int ks = 0; ks < 4; ks++) ldmx4(qf[ks], qpL + ks * 32);

    float mr0 = -INFINITY, mr1 = -INFINITY, lr0 = 0.f, lr1 = 0.f;
    float oa[8][4];
#pragma unroll
    for (int nt = 0; nt < 8; nt++)
#pragma unroll
        for (int j = 0; j < 4; j++) oa[nt][j] = 0.f;

    for (int kt = 0; kt < 32; ++kt) {
        CP_WAIT0();
        __syncthreads();

        if (kt + 1 < 32) {
            const int nb = (kt + 1) & 1;
            const __half* Ks = Kg + (size_t)((kt + 1) * 64 + lrow) * E_;
            const __half* Vs = Vtg + (size_t)lrow * S_ + (kt + 1) * 64;
#pragma unroll
            for (int p = 0; p < 4; ++p) {
                cpasync16(dK + nb * KVBB + p * 16, Ks + lc0 + p * 8);
                cpasync16(dV + nb * KVBB + p * 16, Vs + lc0 + p * 8);
            }
        }
        CP_COMMIT();

        const uint32_t kB = sKb + (kt & 1) * KVBB + BLANE16(lane, APH);
        const uint32_t vB = sVb + (kt & 1) * KVBB + BLANE16(lane, APH);

        // ---- S = Q K^T (log2 domain) ----
        float sc[8][4];
#pragma unroll
        for (int nt = 0; nt < 8; nt++)
#pragma unroll
            for (int j = 0; j < 4; j++) sc[nt][j] = 0.f;

#pragma unroll
        for (int ks = 0; ks < 4; ks++) {
#pragma unroll
            for (int np = 0; np < 4; np++) {
                uint32_t bf[4];
                ldmx4(bf, kB + np * (16 * APH * 2) + ks * 32);
                mma16(sc[np * 2    ], qf[ks], bf[0], bf[1]);
                mma16(sc[np * 2 + 1], qf[ks], bf[2], bf[3]);
            }
        }

        // ---- online softmax, base 2 ----
        float mx0 = -INFINITY, mx1 = -INFINITY;
#pragma unroll
        for (int nt = 0; nt < 8; nt++) {
            mx0 = fmaxf(mx0, fmaxf(sc[nt][0], sc[nt][1]));
            mx1 = fmaxf(mx1, fmaxf(sc[nt][2], sc[nt][3]));
        }
        mx0 = fmaxf(mx0, __shfl_xor_sync(0xffffffffu, mx0, 1));
        mx0 = fmaxf(mx0, __shfl_xor_sync(0xffffffffu, mx0, 2));
        mx1 = fmaxf(mx1, __shfl_xor_sync(0xffffffffu, mx1, 1));
        mx1 = fmaxf(mx1, __shfl_xor_sync(0xffffffffu, mx1, 2));

        const float mn0 = fmaxf(mr0, mx0);
        const float mn1 = fmaxf(mr1, mx1);
        const float c0 = exp2f(mr0 - mn0);
        const float c1 = exp2f(mr1 - mn1);
        mr0 = mn0; mr1 = mn1;

        float rs0 = 0.f, rs1 = 0.f;
#pragma unroll
        for (int nt = 0; nt < 8; nt++) {
            sc[nt][0] = exp2f(sc[nt][0] - mn0); rs0 += sc[nt][0];
            sc[nt][1] = exp2f(sc[nt][1] - mn0); rs0 += sc[nt][1];
            sc[nt][2] = exp2f(sc[nt][2] - mn1); rs1 += sc[nt][2];
            sc[nt][3] = exp2f(sc[nt][3] - mn1); rs1 += sc[nt][3];
        }
        rs0 += __shfl_xor_sync(0xffffffffu, rs0, 1);
        rs0 += __shfl_xor_sync(0xffffffffu, rs0, 2);
        rs1 += __shfl_xor_sync(0xffffffffu, rs1, 1);
        rs1 += __shfl_xor_sync(0xffffffffu, rs1, 2);
        lr0 = lr0 * c0 + rs0;
        lr1 = lr1 * c1 + rs1;

#pragma unroll
        for (int nt = 0; nt < 8; nt++) {
            oa[nt][0] *= c0; oa[nt][1] *= c0;
            oa[nt][2] *= c1; oa[nt][3] *= c1;
        }

        // ---- P -> smem as half2 (warp-local rows of QP region) ----
#pragma unroll
        for (int nt = 0; nt < 8; nt++) {
            const int cc = nt * 8 + 2 * tig;
            *(half2*)&QPh[(r0    ) * APH + cc] = __floats2half2_rn(sc[nt][0], sc[nt][1]);
            *(half2*)&QPh[(r0 + 8) * APH + cc] = __floats2half2_rn(sc[nt][2], sc[nt][3]);
        }
        __syncwarp();

        // ---- PV: oa += P @ V ----
#pragma unroll
        for (int ks = 0; ks < 4; ks++) {
            uint32_t ap[4];
            ldmx4(ap, qpL + ks * 32);
#pragma unroll
            for (int np = 0; np < 4; np++) {
                uint32_t bf[4];
                ldmx4(bf, vB + np * (16 * APH * 2) + ks * 32);
                mma16(oa[np * 2    ], ap, bf[0], bf[1]);
                mma16(oa[np * 2 + 1], ap, bf[2], bf[3]);
            }
        }
        __syncwarp();
    }

    // ---- epilogue: ctx half [b][h][s][d] ----
    const float i0 = 1.0f / lr0;
    const float i1 = 1.0f / lr1;
    __half* Og = g_ctxh + ((size_t)(b * H_ + h) * S_ + q0) * HD_;
#pragma unroll
    for (int nt = 0; nt < 8; nt++) {
        const int col = nt * 8 + 2 * tig;
        *(half2*)(Og + (size_t)(r0    ) * HD_ + col) =
            __floats2half2_rn(oa[nt][0] * i0, oa[nt][1] * i0);
        *(half2*)(Og + (size_t)(r0 + 8) * HD_ + col) =
            __floats2half2_rn(oa[nt][2] * i1, oa[nt][3] * i1);
    }
}

// ============================================================
extern "C" void kernel_launch(void* const* d_in, const int* in_sizes, int n_in,
                              void* d_out, int out_size)
{
    const float* X  = (const float*)d_in[0];
    const float* Wq = (const float*)d_in[1];
    const float* bq = (const float*)d_in[2];
    const float* Wk = (const float*)d_in[3];
    const float* bk = (const float*)d_in[4];
    const float* Wv = (const float*)d_in[5];
    const float* bv = (const float*)d_in[6];
    const float* Wo = (const float*)d_in[7];
    const float* bo = (const float*)d_in[8];
    float* out = (float*)d_out;

    cudaFuncSetAttribute(qkv_kernel,
                         cudaFuncAttributeMaxDynamicSharedMemorySize, GEMM_SMEM);
    cudaFuncSetAttribute(oproj_kernel,
                         cudaFuncAttributeMaxDynamicSharedMemorySize, GEMM_SMEM);
    cudaFuncSetAttribute(attn_kernel,
                         cudaFuncAttributeMaxDynamicSharedMemorySize, ATTN_SMEM);

    // 1. round X + weights to fp16
    prep_kernel<<<dim3(M_ * E_ / (256 * 4), 5), 256>>>(X, Wq, Wk, Wv, Wo);

    // 2. Q/K/V projections (fp16 mma)
    qkv_kernel<<<dim3(E_ / 128, M_ / 128, 3), 256, GEMM_SMEM>>>(bq, bk, bv);

    // 3. attention (fp16 mma flash, 4 CTAs/SM)
    attn_kernel<<<dim3(S_ / TQ, H_, B_), 128, ATTN_SMEM>>>();

    // 4. output projection
    oproj_kernel<<<dim3(E_ / 128, M_ / 128), 256, GEMM_SMEM>>>(bo, out);
}

// round 16
// speedup vs baseline: 1.1294x; 1.1294x over previous
#include <cuda_runtime.h>
#include <cuda_fp16.h>
#include <math.h>
#include <stdint.h>

#define B_  2
#define S_  2048
#define E_  1024
#define H_  16
#define HD_ 64
#define M_  (B_*S_)   // 4096

// Scratch (allocation-free rule: __device__ globals), all fp16
__device__ __half g_Xh[M_*E_];        // rounded X
__device__ __half g_Wh[4][E_*E_];     // rounded Wq,Wk,Wv,Wo
__device__ __half g_Qh[B_*S_*E_];     // * 0.125*log2(e)
__device__ __half g_Kh[B_*S_*E_];
__device__ __half g_Vth[B_*H_*HD_*S_];// [b][h][d][s]
__device__ __half g_ctxh[B_*S_*E_];   // [B][H][S][HD] order

// ============================================================
// helpers
// ============================================================
__device__ __forceinline__ void mma16(float c[4], const uint32_t a[4],
                                      uint32_t b0, uint32_t b1) {
    asm volatile(
        "mma.sync.aligned.m16n8k16.row.col.f32.f16.f16.f32 "
        "{%0,%1,%2,%3}, {%4,%5,%6,%7}, {%8,%9}, {%0,%1,%2,%3};"
        : "+f"(c[0]), "+f"(c[1]), "+f"(c[2]), "+f"(c[3])
        : "r"(a[0]), "r"(a[1]), "r"(a[2]), "r"(a[3]), "r"(b0), "r"(b1));
}

__device__ __forceinline__ void ldmx4(uint32_t r[4], uint32_t addr) {
    asm volatile("ldmatrix.sync.aligned.m8n8.x4.shared.b16 {%0,%1,%2,%3}, [%4];"
                 : "=r"(r[0]), "=r"(r[1]), "=r"(r[2]), "=r"(r[3]) : "r"(addr));
}

__device__ __forceinline__ uint32_t smem_u32(const void* p) {
    uint32_t a;
    asm("{ .reg .u64 t; cvta.to.shared.u64 t, %1; cvt.u32.u64 %0, t; }"
        : "=r"(a) : "l"(p));
    return a;
}

__device__ __forceinline__ void cpasync16(uint32_t dst, const void* src) {
    asm volatile(
        "{ .reg .u64 g; cvta.to.global.u64 g, %1; "
        "cp.async.cg.shared.global [%0], [g], 16; }"
        :: "r"(dst), "l"(src) : "memory");
}
#define CP_COMMIT() asm volatile("cp.async.commit_group;" ::: "memory")
#define CP_WAIT0()  asm volatile("cp.async.wait_group 0;" ::: "memory")
#define CP_WAIT3()  asm volatile("cp.async.wait_group 3;" ::: "memory")

// fp16 ldmatrix lane->byte-offset maps (stride ST in halves)
// A-operand [m][k]: tiles (m0,k0),(m8,k0),(m0,k8),(m8,k8)
#define ALANE16(lane, ST) (((((lane)&7) + (((lane)>>3)&1)*8) * (ST) + ((lane)>>4)*8) * 2)
// B-operand [n][k]: tiles (n0,k0),(n0,k8),(n8,k0),(n8,k8)
#define BLANE16(lane, ST) (((((lane)&7) + ((lane)>>4)*8) * (ST) + (((lane)>>3)&1)*8) * 2)

// ============================================================
// prepass: round X and the 4 weights to fp16
// ============================================================
__global__ __launch_bounds__(256) void prep_kernel(
    const float* __restrict__ X,
    const float* __restrict__ Wq, const float* __restrict__ Wk,
    const float* __restrict__ Wv, const float* __restrict__ Wo)
{
    const int seg = blockIdx.y;
    const float* src; __half* dst; int n;
    if (seg == 0)      { src = X;  dst = g_Xh;    n = M_ * E_; }
    else if (seg == 1) { src = Wq; dst = g_Wh[0]; n = E_ * E_; }
    else if (seg == 2) { src = Wk; dst = g_Wh[1]; n = E_ * E_; }
    else if (seg == 3) { src = Wv; dst = g_Wh[2]; n = E_ * E_; }
    else               { src = Wo; dst = g_Wh[3]; n = E_ * E_; }
    const int i = (blockIdx.x * 256 + threadIdx.x) * 4;
    if (i < n) {
        float4 v = *(const float4*)(src + i);
        *(half2*)(dst + i)     = __floats2half2_rn(v.x, v.y);
        *(half2*)(dst + i + 2) = __floats2half2_rn(v.z, v.w);
    }
}

// ============================================================
// GEMM core (fp16): 128x128 tile, BK=32 halves, 5-stage cp.async (wait 3),
// 256 threads (8 warps 2x4), 4x4 m16n8k16 per warp, ldmatrix frags
// (unchanged — proven R14 structure)
// ============================================================
#define GSTH   40                   // halves per row (32 + 8 pad); 80B rows
#define GBUFB  (128 * GSTH * 2)     // 10240 bytes per stage per matrix
#define GSTAGES 5
#define GEMM_SMEM (GSTAGES * 2 * GBUFB)   // 102400 bytes
#define GNKT   32                   // K = 1024 / 32

__device__ __forceinline__ void gemm_core(const __half* __restrict__ A,
                                          const __half* __restrict__ W,
                                          char* smem,
                                          float acc[4][4][4],
                                          int bm, int bn)
{
    char* As = smem;
    char* Bs = smem + GSTAGES * GBUFB;

    const int tid  = threadIdx.x;
    const int lane = tid & 31;
    const int wid  = tid >> 5;
    const int warp_m = wid >> 2;
    const int warp_n = wid & 3;

    // loader: 2 threads per row, each 2 x 16B chunks (16 halves)
    const int lrow = tid >> 1;           // 0..127
    const int lc0  = (tid & 1) * 16;     // half offset 0 or 16

    const uint32_t sA = smem_u32(As);
    const uint32_t sB = smem_u32(Bs);
    const uint32_t aL = sA + (uint32_t)(warp_m * 64 * GSTH * 2) + ALANE16(lane, GSTH);
    const uint32_t bL = sB + (uint32_t)(warp_n * 32 * GSTH * 2) + BLANE16(lane, GSTH);
    const uint32_t dA = sA + (uint32_t)((lrow * GSTH + lc0) * 2);
    const uint32_t dB = sB + (uint32_t)((lrow * GSTH + lc0) * 2);

    const __half* Ap = A + (size_t)(bm + lrow) * E_ + lc0;
    const __half* Wp = W + (size_t)(bn + lrow) * E_ + lc0;

#pragma unroll
    for (int mi = 0; mi < 4; mi++)
#pragma unroll
        for (int nt = 0; nt < 4; nt++)
#pragma unroll
            for (int j = 0; j < 4; j++) acc[mi][nt][j] = 0.f;

    // prologue: issue stages 0..3
#pragma unroll
    for (int s = 0; s < GSTAGES - 1; ++s) {
        const int k0 = s * 32;
        cpasync16(dA + s * GBUFB,      Ap + k0);
        cpasync16(dA + s * GBUFB + 16, Ap + k0 + 8);
        cpasync16(dB + s * GBUFB,      Wp + k0);
        cpasync16(dB + s * GBUFB + 16, Wp + k0 + 8);
        CP_COMMIT();
    }

    int cslot = 0, wslot = GSTAGES - 1;
    for (int kt = 0; kt < GNKT; ++kt) {
        CP_WAIT3();            // tile kt resident (<=3 groups pending)
        __syncthreads();       // all warps past compute(kt-1); data published

        {   // issue tile kt+4 into wslot (empty commit at tail keeps counts)
            const int t = kt + GSTAGES - 1;
            if (t < GNKT) {
                const int k0 = t * 32;
                cpasync16(dA + wslot * GBUFB,      Ap + k0);
                cpasync16(dA + wslot * GBUFB + 16, Ap + k0 + 8);
                cpasync16(dB + wslot * GBUFB,      Wp + k0);
                cpasync16(dB + wslot * GBUFB + 16, Wp + k0 + 8);
            }
            CP_COMMIT();
        }

        const uint32_t aB = aL + cslot * GBUFB;
        const uint32_t bB = bL + cslot * GBUFB;
#pragma unroll
        for (int ks = 0; ks < 2; ks++) {
            uint32_t af[4][4];
#pragma unroll
            for (int mi = 0; mi < 4; mi++)
                ldmx4(af[mi], aB + mi * (16 * GSTH * 2) + ks * 32);
            uint32_t bf[2][4];
#pragma unroll
            for (int np = 0; np < 2; np++)
                ldmx4(bf[np], bB + np * (16 * GSTH * 2) + ks * 32);
#pragma unroll
            for (int np = 0; np < 2; np++)
#pragma unroll
                for (int hh = 0; hh < 2; hh++) {
                    const int nt = np * 2 + hh;
#pragma unroll
                    for (int mi = 0; mi < 4; mi++)
                        mma16(acc[mi][nt], af[mi], bf[np][hh * 2], bf[np][hh * 2 + 1]);
                }
        }

        cslot = (cslot == GSTAGES - 1) ? 0 : cslot + 1;
        wslot = (wslot == GSTAGES - 1) ? 0 : wslot + 1;
    }
}

// ============================================================
// qkv: X @ W^T + b -> Qh (*0.125*log2e) / Kh / Vth (transposed)
// ============================================================
#define QSCALE (0.125f * 1.4426950408889634f)

__global__ __launch_bounds__(256, 2) void qkv_kernel(
    const float* __restrict__ bq, const float* __restrict__ bk,
    const float* __restrict__ bv)
{
    extern __shared__ char smem[];
    const int z = blockIdx.z;
    const float* bias = (z == 0) ? bq : (z == 1) ? bk : bv;
    const int bm = blockIdx.y * 128;
    const int bn = blockIdx.x * 128;

    float acc[4][4][4];
    gemm_core(g_Xh, g_Wh[z], smem, acc, bm, bn);

    const int lane = threadIdx.x & 31;
    const int wid  = threadIdx.x >> 5;
    const int g    = lane >> 2;
    const int tig  = lane & 3;
    const int warp_m = wid >> 2;
    const int warp_n = wid & 3;

    if (z < 2) {
        __half* C = (z == 0) ? g_Qh : g_Kh;
        const float scale = (z == 0) ? QSCALE : 1.0f;
#pragma unroll
        for (int mi = 0; mi < 4; mi++) {
            const int r0 = bm + warp_m * 64 + mi * 16 + g;
#pragma unroll
            for (int nt = 0; nt < 4; nt++) {
                const int col = bn + warp_n * 32 + nt * 8 + 2 * tig;
                float bx = bias[col], by = bias[col + 1];
                *(half2*)(C + (size_t)r0 * E_ + col) =
                    __floats2half2_rn((acc[mi][nt][0] + bx) * scale,
                                      (acc[mi][nt][1] + by) * scale);
                *(half2*)(C + (size_t)(r0 + 8) * E_ + col) =
                    __floats2half2_rn((acc[mi][nt][2] + bx) * scale,
                                      (acc[mi][nt][3] + by) * scale);
            }
        }
    } else {
        // V: transposed store into g_Vth[b][h][d][s]
#pragma unroll
        for (int mi = 0; mi < 4; mi++) {
            const int r0 = bm + warp_m * 64 + mi * 16 + g;
#pragma unroll
            for (int nt = 0; nt < 4; nt++) {
                const int col = bn + warp_n * 32 + nt * 8 + 2 * tig;
                float bx = bias[col], by = bias[col + 1];
#pragma unroll
                for (int rr = 0; rr < 2; rr++) {
                    const int row = r0 + rr * 8;
                    const int s  = row & (S_ - 1);
                    const int bb = row >> 11;
                    const int h0 = col >> 6, d0 = col & 63;
                    const int h1 = (col + 1) >> 6, d1 = (col + 1) & 63;
                    g_Vth[(((size_t)bb * H_ + h0) * HD_ + d0) * S_ + s] =
                        __float2half_rn(acc[mi][nt][rr * 2 + 0] + bx);
                    g_Vth[(((size_t)bb * H_ + h1) * HD_ + d1) * S_ + s] =
                        __float2half_rn(acc[mi][nt][rr * 2 + 1] + by);
                }
            }
        }
    }
}

// ============================================================
// oproj: ctx @ Wo^T + bo -> out (fp32)
// ============================================================
__global__ __launch_bounds__(256, 2) void oproj_kernel(
    const float* __restrict__ bo, float* __restrict__ out)
{
    extern __shared__ char smem[];
    const int bm = blockIdx.y * 128;
    const int bn = blockIdx.x * 128;

    float acc[4][4][4];
    gemm_core(g_ctxh, g_Wh[3], smem, acc, bm, bn);

    const int lane = threadIdx.x & 31;
    const int wid  = threadIdx.x >> 5;
    const int g    = lane >> 2;
    const int tig  = lane & 3;
    const int warp_m = wid >> 2;
    const int warp_n = wid & 3;

#pragma unroll
    for (int mi = 0; mi < 4; mi++) {
        const int r0 = bm + warp_m * 64 + mi * 16 + g;
#pragma unroll
        for (int nt = 0; nt < 4; nt++) {
            const int col = bn + warp_n * 32 + nt * 8 + 2 * tig;
            float bx = bo[col], by = bo[col + 1];
            *(float2*)(out + (size_t)r0 * E_ + col) =
                make_float2(acc[mi][nt][0] + bx, acc[mi][nt][1] + by);
            *(float2*)(out + (size_t)(r0 + 8) * E_ + col) =
                make_float2(acc[mi][nt][2] + bx, acc[mi][nt][3] + by);
        }
    }
}

// ============================================================
// Flash attention (fp16 mma): 128-query x 64-key tiles, 256 threads
// (R14 shape), cp.async double-buffered K/V, hoisted Q frags,
// base-2 softmax, P kept in REGISTERS for PV (no smem round-trip).
// ============================================================
#define APH   72
#define KVBB  (64 * APH * 2)        // 9216 bytes per K/V buffer
#define ATTN_SMEM (4 * KVBB + 128 * APH * 2)   // 55296 bytes

__global__ __launch_bounds__(256, 2) void attn_kernel()
{
    extern __shared__ char sm[];
    char*   Kb  = sm;                       // [2][64][APH] halves (rows = key)
    char*   Vb  = sm + 2 * KVBB;            // [2][64][APH]  (rows = d, cols = key)
    __half* QPh = (__half*)(sm + 4 * KVBB); // [128][APH]   Q tile

    const int b  = blockIdx.z;
    const int h  = blockIdx.y;
    const int q0 = blockIdx.x * 128;
    const int tid  = threadIdx.x;
    const int lane = tid & 31;
    const int wid  = tid >> 5;
    const int r0   = wid * 16 + (lane >> 2);
    const int tig  = lane & 3;

    const uint32_t sKb = smem_u32(Kb);
    const uint32_t sVb = smem_u32(Vb);
    const uint32_t sQP = smem_u32(QPh);
    const uint32_t qpL = sQP + (uint32_t)(wid * 16 * APH * 2) + ALANE16(lane, APH);

    const __half* Qg  = g_Qh + (size_t)b * S_ * E_ + (size_t)h * HD_;
    const __half* Kg  = g_Kh + (size_t)b * S_ * E_ + (size_t)h * HD_;
    const __half* Vtg = g_Vth + (size_t)(b * H_ + h) * HD_ * S_;

    // K/V loader: 4 threads per row, each 2 x 16B (16 halves)
    const int lrow = tid >> 2;            // 0..63
    const int lc0  = (tid & 3) * 16;      // half offset 0,16,32,48
    const uint32_t dK = sKb + (uint32_t)((lrow * APH + lc0) * 2);
    const uint32_t dV = sVb + (uint32_t)((lrow * APH + lc0) * 2);

    // ---- Q tile fill ----
    {
        const int f8 = (tid & 7) * 8;     // half offset, 16B chunks
        const int rr = tid >> 3;          // 32 rows per pass
#pragma unroll
        for (int p = 0; p < 4; ++p) {
            const int row = p * 32 + rr;
            *(uint4*)&QPh[row * APH + f8] =
                *(const uint4*)(Qg + (size_t)(q0 + row) * E_ + f8);
        }
    }

    // ---- issue K/V tile 0 ----
    {
        const __half* Ks = Kg + (size_t)lrow * E_;
        const __half* Vs = Vtg + (size_t)lrow * S_;
        cpasync16(dK,      Ks + lc0);
        cpasync16(dK + 16, Ks + lc0 + 8);
        cpasync16(dV,      Vs + lc0);
        cpasync16(dV + 16, Vs + lc0 + 8);
        CP_COMMIT();
    }

    __syncthreads();   // Q tile visible

    // hoist Q fragments: 4 k16-steps
    uint32_t qf[4][4];
#pragma unroll
    for (int ks = 0; ks < 4; ks++) ldmx4(qf[ks], qpL + ks * 32);

    float mr0 = -INFINITY, mr1 = -INFINITY, lr0 = 0.f, lr1 = 0.f;
    float oa[8][4];
#pragma unroll
    for (int nt = 0; nt < 8; nt++)
#pragma unroll
        for (int j = 0; j < 4; j++) oa[nt][j] = 0.f;

    for (int kt = 0; kt < 32; ++kt) {
        CP_WAIT0();
        __syncthreads();

        if (kt + 1 < 32) {
            const int nb = (kt + 1) & 1;
            const __half* Ks = Kg + (size_t)((kt + 1) * 64 + lrow) * E_;
            const __half* Vs = Vtg + (size_t)lrow * S_ + (kt + 1) * 64;
            cpasync16(dK + nb * KVBB,      Ks + lc0);
            cpasync16(dK + nb * KVBB + 16, Ks + lc0 + 8);
            cpasync16(dV + nb * KVBB,      Vs + lc0);
            cpasync16(dV + nb * KVBB + 16, Vs + lc0 + 8);
        }
        CP_COMMIT();

        const uint32_t kB = sKb + (kt & 1) * KVBB + BLANE16(lane, APH);
        const uint32_t vB = sVb + (kt & 1) * KVBB + BLANE16(lane, APH);

        // ---- S = Q K^T (log2 domain) ----
        float sc[8][4];
#pragma unroll
        for (int nt = 0; nt < 8; nt++)
#pragma unroll
            for (int j = 0; j < 4; j++) sc[nt][j] = 0.f;

#pragma unroll
        for (int ks = 0; ks < 4; ks++) {
#pragma unroll
            for (int np = 0; np < 4; np++) {
                uint32_t bf[4];
                ldmx4(bf, kB + np * (16 * APH * 2) + ks * 32);
                mma16(sc[np * 2    ], qf[ks], bf[0], bf[1]);
                mma16(sc[np * 2 + 1], qf[ks], bf[2], bf[3]);
            }
        }

        // ---- online softmax, base 2 ----
        float mx0 = -INFINITY, mx1 = -INFINITY;
#pragma unroll
        for (int nt = 0; nt < 8; nt++) {
            mx0 = fmaxf(mx0, fmaxf(sc[nt][0], sc[nt][1]));
            mx1 = fmaxf(mx1, fmaxf(sc[nt][2], sc[nt][3]));
        }
        mx0 = fmaxf(mx0, __shfl_xor_sync(0xffffffffu, mx0, 1));
        mx0 = fmaxf(mx0, __shfl_xor_sync(0xffffffffu, mx0, 2));
        mx1 = fmaxf(mx1, __shfl_xor_sync(0xffffffffu, mx1, 1));
        mx1 = fmaxf(mx1, __shfl_xor_sync(0xffffffffu, mx1, 2));

        const float mn0 = fmaxf(mr0, mx0);
        const float mn1 = fmaxf(mr1, mx1);
        const float c0 = exp2f(mr0 - mn0);
        const float c1 = exp2f(mr1 - mn1);
        mr0 = mn0; mr1 = mn1;

        float rs0 = 0.f, rs1 = 0.f;
#pragma unroll
        for (int nt = 0; nt < 8; nt++) {
            sc[nt][0] = exp2f(sc[nt][0] - mn0); rs0 += sc[nt][0];
            sc[nt][1] = exp2f(sc[nt][1] - mn0); rs0 += sc[nt][1];
            sc[nt][2] = exp2f(sc[nt][2] - mn1); rs1 += sc[nt][2];
            sc[nt][3] = exp2f(sc[nt][3] - mn1); rs1 += sc[nt][3];
        }
        rs0 += __shfl_xor_sync(0xffffffffu, rs0, 1);
        rs0 += __shfl_xor_sync(0xffffffffu, rs0, 2);
        rs1 += __shfl_xor_sync(0xffffffffu, rs1, 1);
        rs1 += __shfl_xor_sync(0xffffffffu, rs1, 2);
        lr0 = lr0 * c0 + rs0;
        lr1 = lr1 * c1 + rs1;

#pragma unroll
        for (int nt = 0; nt < 8; nt++) {
            oa[nt][0] *= c0; oa[nt][1] *= c0;
            oa[nt][2] *= c1; oa[nt][3] *= c1;
        }

        // ---- P fragments in registers (S-accum layout == PV A-operand layout):
        // k-step ks covers keys 16ks..16ks+15:
        //   ap[0]=(row g,   keys 16ks+2tig..+1) = sc[2ks][0..1]
        //   ap[1]=(row g+8, same)               = sc[2ks][2..3]
        //   ap[2]=(row g,   keys 16ks+8+2tig)   = sc[2ks+1][0..1]
        //   ap[3]=(row g+8, same)               = sc[2ks+1][2..3]
#pragma unroll
        for (int ks = 0; ks < 4; ks++) {
            uint32_t ap[4];
            half2 p0 = __floats2half2_rn(sc[2*ks  ][0], sc[2*ks  ][1]);
            half2 p1 = __floats2half2_rn(sc[2*ks  ][2], sc[2*ks  ][3]);
            half2 p2 = __floats2half2_rn(sc[2*ks+1][0], sc[2*ks+1][1]);
            half2 p3 = __floats2half2_rn(sc[2*ks+1][2], sc[2*ks+1][3]);
            ap[0] = *(uint32_t*)&p0;
            ap[1] = *(uint32_t*)&p1;
            ap[2] = *(uint32_t*)&p2;
            ap[3] = *(uint32_t*)&p3;
#pragma unroll
            for (int np = 0; np < 4; np++) {
                uint32_t bf[4];
                ldmx4(bf, vB + np * (16 * APH * 2) + ks * 32);
                mma16(oa[np * 2    ], ap, bf[0], bf[1]);
                mma16(oa[np * 2 + 1], ap, bf[2], bf[3]);
            }
        }
    }

    // ---- epilogue: ctx half [b][h][s][d] ----
    const float i0 = 1.0f / lr0;
    const float i1 = 1.0f / lr1;
    __half* Og = g_ctxh + ((size_t)(b * H_ + h) * S_ + q0) * HD_;
#pragma unroll
    for (int nt = 0; nt < 8; nt++) {
        const int col = nt * 8 + 2 * tig;
        *(half2*)(Og + (size_t)(r0    ) * HD_ + col) =
            __floats2half2_rn(oa[nt][0] * i0, oa[nt][1] * i0);
        *(half2*)(Og + (size_t)(r0 + 8) * HD_ + col) =
            __floats2half2_rn(oa[nt][2] * i1, oa[nt][3] * i1);
    }
}

// ============================================================
extern "C" void kernel_launch(void* const* d_in, const int* in_sizes, int n_in,
                              void* d_out, int out_size)
{
    const float* X  = (const float*)d_in[0];
    const float* Wq = (const float*)d_in[1];
    const float* bq = (const float*)d_in[2];
    const float* Wk = (const float*)d_in[3];
    const float* bk = (const float*)d_in[4];
    const float* Wv = (const float*)d_in[5];
    const float* bv = (const float*)d_in[6];
    const float* Wo = (const float*)d_in[7];
    const float* bo = (const float*)d_in[8];
    float* out = (float*)d_out;

    cudaFuncSetAttribute(qkv_kernel,
                         cudaFuncAttributeMaxDynamicSharedMemorySize, GEMM_SMEM);
    cudaFuncSetAttribute(oproj_kernel,
                         cudaFuncAttributeMaxDynamicSharedMemorySize, GEMM_SMEM);
    cudaFuncSetAttribute(attn_kernel,
                         cudaFuncAttributeMaxDynamicSharedMemorySize, ATTN_SMEM);

    // 1. round X + weights to fp16
    prep_kernel<<<dim3(M_ * E_ / (256 * 4), 5), 256>>>(X, Wq, Wk, Wv, Wo);

    // 2. Q/K/V projections (fp16 mma)
    qkv_kernel<<<dim3(E_ / 128, M_ / 128, 3), 256, GEMM_SMEM>>>(bq, bk, bv);

    // 3. attention (fp16 mma flash, P-in-registers)
    attn_kernel<<<dim3(S_ / 128, H_, B_), 256, ATTN_SMEM>>>();

    // 4. output projection
    oproj_kernel<<<dim3(E_ / 128, M_ / 128), 256, GEMM_SMEM>>>(bo, out);
}